// round 1
// baseline (speedup 1.0000x reference)
#include <cuda_runtime.h>
#include <cstdint>

// Problem constants
#define B_    2
#define S_    1024
#define D_    1024
#define H_    16
#define L_    4
#define DFF_  4096
#define ROWS_ (B_*S_)   // 2048

// ---------------- scratch (static device globals; no allocs) ----------------
__device__ float g_x   [ROWS_*D_];
__device__ float g_q   [ROWS_*D_];
__device__ float g_k   [ROWS_*D_];
__device__ float g_v   [ROWS_*D_];
__device__ float g_attn[ROWS_*D_];
__device__ float g_obuf[ROWS_*D_];
__device__ float g_ff1 [ROWS_*DFF_];
__device__ float g_hid [3*ROWS_*D_];

// ---------------- f32x2 packed helpers ----------------
__device__ __forceinline__ unsigned long long pk2(float x, float y) {
    unsigned long long r;
    asm("mov.b64 %0, {%1, %2};" : "=l"(r) : "f"(x), "f"(y));
    return r;
}
__device__ __forceinline__ void fma2(unsigned long long &d, unsigned long long a, unsigned long long b) {
    asm("fma.rn.f32x2 %0, %1, %2, %0;" : "+l"(d) : "l"(a), "l"(b));
}
__device__ __forceinline__ float2 up2(unsigned long long v) {
    float2 f;
    asm("mov.b64 {%0, %1}, %2;" : "=f"(f.x), "=f"(f.y) : "l"(v));
    return f;
}

// ---------------- embed: x = src*emb_w + emb_b + pe ----------------
__global__ void embed_kernel(const float* __restrict__ src, const float* __restrict__ ew,
                             const float* __restrict__ eb, const float* __restrict__ pe)
{
    int i4  = blockIdx.x * 256 + threadIdx.x;     // over ROWS_*D_/4 = 524288
    int row = i4 >> 8;                            // 256 float4 per row
    int c   = (i4 & 255) << 2;
    int s   = row & (S_ - 1);
    float sv = src[row];
    float4 e = *(const float4*)(ew + c);
    float4 b = *(const float4*)(eb + c);
    float4 p = *(const float4*)(pe + (size_t)s * D_ + c);
    float4 o;
    o.x = sv * e.x + b.x + p.x;
    o.y = sv * e.y + b.y + p.y;
    o.z = sv * e.z + b.z + p.z;
    o.w = sv * e.w + b.w + p.w;
    *(float4*)(g_x + (size_t)row * D_ + c) = o;
}

// ---------------- SGEMM: C[M,N] = A[M,K] @ B[K,N] + bias (opt relu) ----------------
// 128x128 tile, BK=8, 256 threads, 8x8 per thread, f32x2 packed over the M (row) pairs.
__global__ void __launch_bounds__(256)
sgemm_kernel(const float* __restrict__ A, const float* __restrict__ Bm,
             const float* __restrict__ bias, float* __restrict__ C,
             int M, int N, int K, int relu)
{
    __shared__ float As[8][128];   // transposed A tile
    __shared__ float Bs[8][128];
    const int tid = threadIdx.x;
    const int bx = blockIdx.x, by = blockIdx.y;
    const int trow = tid >> 1, tseg = (tid & 1) * 4;
    const int brow = tid >> 5, bcol = (tid & 31) * 4;
    const int ty = tid >> 4,  tx = tid & 15;

    const float* Ap = A  + (size_t)(by * 128 + trow) * K + tseg;
    const float* Bp = Bm + (size_t)brow * N + bx * 128 + bcol;

    unsigned long long acc[4][8];
#pragma unroll
    for (int p = 0; p < 4; p++)
#pragma unroll
        for (int j = 0; j < 8; j++) acc[p][j] = 0ull;

    for (int k0 = 0; k0 < K; k0 += 8) {
        float4 av = *(const float4*)(Ap + k0);
        float4 bv = *(const float4*)(Bp + (size_t)k0 * N);
        As[tseg + 0][trow] = av.x;
        As[tseg + 1][trow] = av.y;
        As[tseg + 2][trow] = av.z;
        As[tseg + 3][trow] = av.w;
        *(float4*)&Bs[brow][bcol] = bv;
        __syncthreads();
#pragma unroll
        for (int kk = 0; kk < 8; kk++) {
            const unsigned long long* a64 = (const unsigned long long*)&As[kk][ty * 8];
            float4 b0 = *(const float4*)&Bs[kk][tx * 8];
            float4 b1 = *(const float4*)&Bs[kk][tx * 8 + 4];
            unsigned long long bd[8];
            bd[0] = pk2(b0.x, b0.x); bd[1] = pk2(b0.y, b0.y);
            bd[2] = pk2(b0.z, b0.z); bd[3] = pk2(b0.w, b0.w);
            bd[4] = pk2(b1.x, b1.x); bd[5] = pk2(b1.y, b1.y);
            bd[6] = pk2(b1.z, b1.z); bd[7] = pk2(b1.w, b1.w);
#pragma unroll
            for (int p = 0; p < 4; p++) {
                unsigned long long a2 = a64[p];
#pragma unroll
                for (int j = 0; j < 8; j++) fma2(acc[p][j], a2, bd[j]);
            }
        }
        __syncthreads();
    }

    const int colb = bx * 128 + tx * 8;
    float4 g0 = *(const float4*)(bias + colb);
    float4 g1 = *(const float4*)(bias + colb + 4);
    float bs_[8] = {g0.x, g0.y, g0.z, g0.w, g1.x, g1.y, g1.z, g1.w};

#pragma unroll
    for (int p = 0; p < 4; p++) {
        float2 f[8];
#pragma unroll
        for (int j = 0; j < 8; j++) f[j] = up2(acc[p][j]);
#pragma unroll
        for (int half = 0; half < 2; half++) {
            int row = by * 128 + ty * 8 + 2 * p + half;
            float v[8];
#pragma unroll
            for (int j = 0; j < 8; j++) {
                float val = (half ? f[j].y : f[j].x) + bs_[j];
                v[j] = relu ? fmaxf(val, 0.0f) : val;
            }
            float4 o0 = {v[0], v[1], v[2], v[3]};
            float4 o1 = {v[4], v[5], v[6], v[7]};
            *(float4*)(C + (size_t)row * N + colb)     = o0;
            *(float4*)(C + (size_t)row * N + colb + 4) = o1;
        }
    }
}

// ---------------- fused causal attention (flash-style) ----------------
// grid (qtiles=16, B*H=32), 256 threads. Q tile 64 rows, KV tile 64 rows, DK=64.
// thread t: q-row r = t>>2, sub = t&3 owns dk cols sub*16..+15 and keys j = sub + 4*jj.
// SMEM: qs[64][68], kp[64][68] (K tile, reused for P tile), vs[64][68] -> 52224 B dynamic.
__global__ void attn_kernel(const float* __restrict__ Q, const float* __restrict__ Kg,
                            const float* __restrict__ Vg, float* __restrict__ Og)
{
    extern __shared__ float sm[];
    float* qs = sm;
    float* kp = sm + 64 * 68;
    float* vs = sm + 2 * 64 * 68;

    const int qt = blockIdx.x, bh = blockIdx.y;
    const int b = bh >> 4, h = bh & 15;
    const int tid = threadIdx.x;
    const int r = tid >> 2, sub = tid & 3;
    const size_t base = ((size_t)b * S_) * D_ + (size_t)h * 64;

    const float* qb = Q + base + (size_t)(qt * 64) * D_;
    for (int idx = tid; idx < 1024; idx += 256) {
        int rr = idx >> 4, c = (idx & 15) << 2;
        float4 v = *(const float4*)(qb + (size_t)rr * D_ + c);
        float4 vv = {v.x * 0.125f, v.y * 0.125f, v.z * 0.125f, v.w * 0.125f};
        *(float4*)&qs[rr * 68 + c] = vv;
    }

    float acc[16];
#pragma unroll
    for (int i = 0; i < 16; i++) acc[i] = 0.0f;
    float l = 0.0f, m = -1e30f;
    const int qglob = qt * 64 + r;

    for (int kt = 0; kt <= qt; kt++) {
        __syncthreads();
        const float* kb = Kg + base + (size_t)(kt * 64) * D_;
        const float* vb = Vg + base + (size_t)(kt * 64) * D_;
        for (int idx = tid; idx < 1024; idx += 256) {
            int rr = idx >> 4, c = (idx & 15) << 2;
            *(float4*)&kp[rr * 68 + c] = *(const float4*)(kb + (size_t)rr * D_ + c);
            *(float4*)&vs[rr * 68 + c] = *(const float4*)(vb + (size_t)rr * D_ + c);
        }
        __syncthreads();

        float s[16];
#pragma unroll
        for (int jj = 0; jj < 16; jj++) s[jj] = 0.0f;
#pragma unroll 4
        for (int d = 0; d < 64; d++) {
            float qd = qs[r * 68 + d];
#pragma unroll
            for (int jj = 0; jj < 16; jj++)
                s[jj] += qd * kp[(sub + (jj << 2)) * 68 + d];
        }
#pragma unroll
        for (int jj = 0; jj < 16; jj++) {
            int kg = kt * 64 + sub + (jj << 2);
            if (kg > qglob) s[jj] = -1e30f;
        }
        float mt = s[0];
#pragma unroll
        for (int jj = 1; jj < 16; jj++) mt = fmaxf(mt, s[jj]);
        mt = fmaxf(mt, __shfl_xor_sync(0xffffffffu, mt, 1));
        mt = fmaxf(mt, __shfl_xor_sync(0xffffffffu, mt, 2));
        float mnew = fmaxf(m, mt);
        float corr = __expf(m - mnew);
        float p[16];
        float ls = 0.0f;
#pragma unroll
        for (int jj = 0; jj < 16; jj++) { p[jj] = __expf(s[jj] - mnew); ls += p[jj]; }
        ls += __shfl_xor_sync(0xffffffffu, ls, 1);
        ls += __shfl_xor_sync(0xffffffffu, ls, 2);
        l = l * corr + ls;
        m = mnew;
#pragma unroll
        for (int i = 0; i < 16; i++) acc[i] *= corr;

        __syncthreads();   // all warps done reading K before P overwrites it
#pragma unroll
        for (int jj = 0; jj < 16; jj++) kp[r * 68 + sub + (jj << 2)] = p[jj];
        __syncwarp();
#pragma unroll 2
        for (int j = 0; j < 64; j++) {
            float pj = kp[r * 68 + j];
            float4 v0 = *(const float4*)&vs[j * 68 + sub * 16];
            float4 v1 = *(const float4*)&vs[j * 68 + sub * 16 + 4];
            float4 v2 = *(const float4*)&vs[j * 68 + sub * 16 + 8];
            float4 v3 = *(const float4*)&vs[j * 68 + sub * 16 + 12];
            acc[0]  += pj * v0.x; acc[1]  += pj * v0.y; acc[2]  += pj * v0.z; acc[3]  += pj * v0.w;
            acc[4]  += pj * v1.x; acc[5]  += pj * v1.y; acc[6]  += pj * v1.z; acc[7]  += pj * v1.w;
            acc[8]  += pj * v2.x; acc[9]  += pj * v2.y; acc[10] += pj * v2.z; acc[11] += pj * v2.w;
            acc[12] += pj * v3.x; acc[13] += pj * v3.y; acc[14] += pj * v3.z; acc[15] += pj * v3.w;
        }
    }

    float inv = 1.0f / (l + 1e-9f);
    float* ob = Og + base + (size_t)qglob * D_ + sub * 16;
    float4 o0 = {acc[0] * inv,  acc[1] * inv,  acc[2] * inv,  acc[3] * inv};
    float4 o1 = {acc[4] * inv,  acc[5] * inv,  acc[6] * inv,  acc[7] * inv};
    float4 o2 = {acc[8] * inv,  acc[9] * inv,  acc[10] * inv, acc[11] * inv};
    float4 o3 = {acc[12] * inv, acc[13] * inv, acc[14] * inv, acc[15] * inv};
    *(float4*)(ob)      = o0;
    *(float4*)(ob + 4)  = o1;
    *(float4*)(ob + 8)  = o2;
    *(float4*)(ob + 12) = o3;
}

// ---------------- t = x + delta; out = LN(t)*g + b + delta  (the quirk) ----------------
__global__ void add_ln_kernel(const float* __restrict__ x, const float* __restrict__ dl,
                              const float* __restrict__ g, const float* __restrict__ bb,
                              float* __restrict__ out)
{
    const int row = blockIdx.x, tid = threadIdx.x;   // 256 threads, 4 elems each
    const float4* xr = (const float4*)(x  + (size_t)row * D_);
    const float4* dr = (const float4*)(dl + (size_t)row * D_);
    float4 xv = xr[tid], dv = dr[tid];
    float4 t = {xv.x + dv.x, xv.y + dv.y, xv.z + dv.z, xv.w + dv.w};

    __shared__ float red[8];
    float s = t.x + t.y + t.z + t.w;
#pragma unroll
    for (int off = 16; off; off >>= 1) s += __shfl_xor_sync(0xffffffffu, s, off);
    if ((tid & 31) == 0) red[tid >> 5] = s;
    __syncthreads();
    float mu = (red[0] + red[1] + red[2] + red[3] + red[4] + red[5] + red[6] + red[7]) * (1.0f / D_);
    __syncthreads();

    float d0 = t.x - mu, d1 = t.y - mu, d2 = t.z - mu, d3 = t.w - mu;
    float sq = d0 * d0 + d1 * d1 + d2 * d2 + d3 * d3;
#pragma unroll
    for (int off = 16; off; off >>= 1) sq += __shfl_xor_sync(0xffffffffu, sq, off);
    if ((tid & 31) == 0) red[tid >> 5] = sq;
    __syncthreads();
    float var = (red[0] + red[1] + red[2] + red[3] + red[4] + red[5] + red[6] + red[7]) * (1.0f / D_);
    float rinv = rsqrtf(var + 1e-5f);

    float4 gv = ((const float4*)g)[tid];
    float4 bv = ((const float4*)bb)[tid];
    float4 o;
    o.x = d0 * rinv * gv.x + bv.x + dv.x;
    o.y = d1 * rinv * gv.y + bv.y + dv.y;
    o.z = d2 * rinv * gv.z + bv.z + dv.z;
    o.w = d3 * rinv * gv.w + bv.w + dv.w;
    ((float4*)(out + (size_t)row * D_))[tid] = o;
}

// ---------------- head reduce: out[bs,o] = hid[o,bs,:] . hw2[o] + hb2[o] ----------------
__global__ void head_reduce_kernel(const float* __restrict__ hid, const float* __restrict__ w2,
                                   const float* __restrict__ b2, float* __restrict__ out)
{
    const int bs = blockIdx.x, o = blockIdx.y;
    const float4* hr = (const float4*)(hid + ((size_t)o * ROWS_ + bs) * D_);
    const float4* wr = (const float4*)(w2 + (size_t)o * D_);
    const int tid = threadIdx.x;
    float4 hv = hr[tid], wv = wr[tid];
    float s = hv.x * wv.x + hv.y * wv.y + hv.z * wv.z + hv.w * wv.w;
#pragma unroll
    for (int off = 16; off; off >>= 1) s += __shfl_xor_sync(0xffffffffu, s, off);
    __shared__ float red[8];
    if ((tid & 31) == 0) red[tid >> 5] = s;
    __syncthreads();
    if (tid == 0) {
        float t = red[0] + red[1] + red[2] + red[3] + red[4] + red[5] + red[6] + red[7];
        out[bs * 3 + o] = t + b2[o];
    }
}

// ---------------- launch ----------------
extern "C" void kernel_launch(void* const* d_in, const int* in_sizes, int n_in,
                              void* d_out, int out_size)
{
    const float* src   = (const float*)d_in[0];
    const float* emb_w = (const float*)d_in[1];
    const float* emb_b = (const float*)d_in[2];
    const float* pe    = (const float*)d_in[3];
    const float* Wq    = (const float*)d_in[4];
    const float* bq    = (const float*)d_in[5];
    const float* Wk    = (const float*)d_in[6];
    const float* bk    = (const float*)d_in[7];
    const float* Wv    = (const float*)d_in[8];
    const float* bv    = (const float*)d_in[9];
    const float* Wo    = (const float*)d_in[10];
    const float* bo    = (const float*)d_in[11];
    const float* fc1_w = (const float*)d_in[12];
    const float* fc1_b = (const float*)d_in[13];
    const float* fc2_w = (const float*)d_in[14];
    const float* fc2_b = (const float*)d_in[15];
    const float* ln1_g = (const float*)d_in[16];
    const float* ln1_b = (const float*)d_in[17];
    const float* ln2_g = (const float*)d_in[18];
    const float* ln2_b = (const float*)d_in[19];
    const float* hw1   = (const float*)d_in[20];
    const float* hb1   = (const float*)d_in[21];
    const float* hw2   = (const float*)d_in[22];
    const float* hb2   = (const float*)d_in[23];

    float *x, *q, *k, *v, *attn, *obuf, *ff1, *hid;
    cudaGetSymbolAddress((void**)&x,    g_x);
    cudaGetSymbolAddress((void**)&q,    g_q);
    cudaGetSymbolAddress((void**)&k,    g_k);
    cudaGetSymbolAddress((void**)&v,    g_v);
    cudaGetSymbolAddress((void**)&attn, g_attn);
    cudaGetSymbolAddress((void**)&obuf, g_obuf);
    cudaGetSymbolAddress((void**)&ff1,  g_ff1);
    cudaGetSymbolAddress((void**)&hid,  g_hid);

    const int ATTN_SMEM = 3 * 64 * 68 * 4;  // 52224 B
    cudaFuncSetAttribute(attn_kernel, cudaFuncAttributeMaxDynamicSharedMemorySize, ATTN_SMEM);

    embed_kernel<<<ROWS_ * D_ / 4 / 256, 256>>>(src, emb_w, emb_b, pe);

    const dim3 gDxD(D_ / 128, ROWS_ / 128);       // (8,16)
    const dim3 gDxF(DFF_ / 128, ROWS_ / 128);     // (32,16)
    for (int l = 0; l < L_; l++) {
        size_t wof = (size_t)l * D_ * D_;
        size_t bof = (size_t)l * D_;
        sgemm_kernel<<<gDxD, 256>>>(x, Wq + wof, bq + bof, q, ROWS_, D_, D_, 0);
        sgemm_kernel<<<gDxD, 256>>>(x, Wk + wof, bk + bof, k, ROWS_, D_, D_, 0);
        sgemm_kernel<<<gDxD, 256>>>(x, Wv + wof, bv + bof, v, ROWS_, D_, D_, 0);
        attn_kernel<<<dim3(S_ / 64, B_ * H_), 256, ATTN_SMEM>>>(q, k, v, attn);
        sgemm_kernel<<<gDxD, 256>>>(attn, Wo + wof, bo + bof, obuf, ROWS_, D_, D_, 0);
        add_ln_kernel<<<ROWS_, 256>>>(x, obuf, ln1_g + bof, ln1_b + bof, x);
        sgemm_kernel<<<gDxF, 256>>>(x, fc1_w + (size_t)l * D_ * DFF_, fc1_b + (size_t)l * DFF_,
                                    ff1, ROWS_, DFF_, D_, 1);
        sgemm_kernel<<<gDxD, 256>>>(ff1, fc2_w + (size_t)l * DFF_ * D_, fc2_b + bof,
                                    obuf, ROWS_, D_, DFF_, 1);
        add_ln_kernel<<<ROWS_, 256>>>(x, obuf, ln2_g + bof, ln2_b + bof, x);
    }

    for (int o = 0; o < 3; o++)
        sgemm_kernel<<<gDxD, 256>>>(x, hw1 + (size_t)o * D_ * D_, hb1 + (size_t)o * D_,
                                    hid + (size_t)o * ROWS_ * D_, ROWS_, D_, D_, 1);
    head_reduce_kernel<<<dim3(ROWS_, 3), 256>>>(hid, hw2, hb2, (float*)d_out);
}

// round 3
// speedup vs baseline: 2.0434x; 2.0434x over previous
#include <cuda_runtime.h>
#include <cuda_bf16.h>
#include <cstdint>

// Problem constants
#define B_    2
#define S_    1024
#define D_    1024
#define H_    16
#define L_    4
#define DFF_  4096
#define ROWS_ (B_*S_)   // 2048

// ---------------- scratch (static device globals; no allocs) ----------------
__device__ float g_x   [ROWS_*D_];
__device__ float g_qkv [ROWS_*3*D_];
__device__ float g_attn[ROWS_*D_];
__device__ float g_obuf[ROWS_*D_];
__device__ float g_ff1 [ROWS_*DFF_];
__device__ float g_hid [ROWS_*3*D_];
__device__ float g_bqkv[L_*3*D_];

__device__ __nv_bfloat16 g_aext[ROWS_*3*DFF_];                 // activations extended-K (max K=4096)
__device__ __nv_bfloat16 g_wqkv[L_*3*D_*3*D_];                 // [3072, 3072] per layer
__device__ __nv_bfloat16 g_wo  [L_*D_*3*D_];                   // [1024, 3072] per layer
__device__ __nv_bfloat16 g_wf1 [L_*DFF_*3*D_];                 // [4096, 3072] per layer
__device__ __nv_bfloat16 g_wf2 [L_*D_*3*DFF_];                 // [1024, 12288] per layer
__device__ __nv_bfloat16 g_wh  [3*D_*3*D_];                    // [3072, 3072]

// ---------------- helpers ----------------
__device__ __forceinline__ uint32_t smem_u32(const void* p) {
    uint32_t a;
    asm("{ .reg .u64 t; cvta.to.shared.u64 t, %1; cvt.u32.u64 %0, t; }" : "=r"(a) : "l"(p));
    return a;
}
__device__ __forceinline__ void ldm_x4(uint32_t& r0, uint32_t& r1, uint32_t& r2, uint32_t& r3, uint32_t addr) {
    asm volatile("ldmatrix.sync.aligned.m8n8.x4.shared.b16 {%0,%1,%2,%3}, [%4];"
                 : "=r"(r0), "=r"(r1), "=r"(r2), "=r"(r3) : "r"(addr));
}
__device__ __forceinline__ void mma16816(float* d, const uint32_t* a, uint32_t b0, uint32_t b1) {
    asm volatile(
        "mma.sync.aligned.m16n8k16.row.col.f32.bf16.bf16.f32 "
        "{%0,%1,%2,%3}, {%4,%5,%6,%7}, {%8,%9}, {%0,%1,%2,%3};"
        : "+f"(d[0]), "+f"(d[1]), "+f"(d[2]), "+f"(d[3])
        : "r"(a[0]), "r"(a[1]), "r"(a[2]), "r"(a[3]), "r"(b0), "r"(b1));
}
__device__ __forceinline__ void cp16(uint32_t saddr, const void* gaddr) {
    asm volatile("cp.async.cg.shared.global [%0], [%1], 16;" :: "r"(saddr), "l"(gaddr));
}
#define CP_COMMIT() asm volatile("cp.async.commit_group;" ::: "memory")

// swizzled smem offset within a [128 rows x 64B] tile: 16B chunk kc of row r
__device__ __forceinline__ int swz(int r, int kc) {
    return r * 64 + ((kc ^ ((r >> 1) & 3)) << 4);
}

// ---------------- embed: x = src*emb_w + emb_b + pe ----------------
__global__ void embed_kernel(const float* __restrict__ src, const float* __restrict__ ew,
                             const float* __restrict__ eb, const float* __restrict__ pe)
{
    int i4  = blockIdx.x * 256 + threadIdx.x;
    int row = i4 >> 8;
    int c   = (i4 & 255) << 2;
    int s   = row & (S_ - 1);
    float sv = src[row];
    float4 e = *(const float4*)(ew + c);
    float4 b = *(const float4*)(eb + c);
    float4 p = *(const float4*)(pe + (size_t)s * D_ + c);
    float4 o;
    o.x = sv * e.x + b.x + p.x;
    o.y = sv * e.y + b.y + p.y;
    o.z = sv * e.z + b.z + p.z;
    o.w = sv * e.w + b.w + p.w;
    *(float4*)(g_x + (size_t)row * D_ + c) = o;
}

// ---------------- activation fp32 -> extended-K bf16 [hi | hi | lo] ----------------
__global__ void conv_act(const float* __restrict__ X, __nv_bfloat16* __restrict__ A, int K)
{
    int idx = blockIdx.x * 256 + threadIdx.x;      // over M*K/4
    int rowlen = K >> 2;
    int r = idx / rowlen;
    int c4 = idx - r * rowlen;
    float4 v = ((const float4*)X)[idx];
    __nv_bfloat16 h0 = __float2bfloat16(v.x), h1 = __float2bfloat16(v.y);
    __nv_bfloat16 h2 = __float2bfloat16(v.z), h3 = __float2bfloat16(v.w);
    __nv_bfloat16 l0 = __float2bfloat16(v.x - __bfloat162float(h0));
    __nv_bfloat16 l1 = __float2bfloat16(v.y - __bfloat162float(h1));
    __nv_bfloat16 l2 = __float2bfloat16(v.z - __bfloat162float(h2));
    __nv_bfloat16 l3 = __float2bfloat16(v.w - __bfloat162float(h3));
    __nv_bfloat162 hA = {h0, h1}, hB = {h2, h3};
    __nv_bfloat162 lA = {l0, l1}, lB = {l2, l3};
    size_t base = (size_t)r * 3 * K + c4 * 4;
    *(__nv_bfloat162*)(A + base)             = hA;
    *(__nv_bfloat162*)(A + base + 2)         = hB;
    *(__nv_bfloat162*)(A + base + K)         = hA;
    *(__nv_bfloat162*)(A + base + K + 2)     = hB;
    *(__nv_bfloat162*)(A + base + 2 * K)     = lA;
    *(__nv_bfloat162*)(A + base + 2 * K + 2) = lB;
}

// ---------------- weight fp32 [K,N] -> transposed extended-K bf16 [N, 3K] = [hi | lo | hi] ----------------
__global__ void conv_wt(const float* __restrict__ W, __nv_bfloat16* __restrict__ Bt, int K, int N)
{
    __shared__ float t[32][33];
    int n0 = blockIdx.x * 32, k0 = blockIdx.y * 32;
    int tx = threadIdx.x, ty = threadIdx.y;      // 32 x 8
#pragma unroll
    for (int j = 0; j < 4; j++)
        t[ty * 4 + j][tx] = W[(size_t)(k0 + ty * 4 + j) * N + n0 + tx];
    __syncthreads();
    int K3 = 3 * K;
#pragma unroll
    for (int j = 0; j < 4; j++) {
        int n = n0 + ty * 4 + j, k = k0 + tx;
        float v = t[tx][ty * 4 + j];
        __nv_bfloat16 hi = __float2bfloat16(v);
        __nv_bfloat16 lo = __float2bfloat16(v - __bfloat162float(hi));
        Bt[(size_t)n * K3 + k]         = hi;
        Bt[(size_t)n * K3 + K + k]     = lo;
        Bt[(size_t)n * K3 + 2 * K + k] = hi;
    }
}

// ---------------- pack QKV biases: [L][3072] ----------------
__global__ void pack_bias(const float* __restrict__ bq, const float* __restrict__ bk,
                          const float* __restrict__ bv, float* __restrict__ dst)
{
    int i = blockIdx.x * 256 + threadIdx.x;      // L*3072
    int l = i / 3072, r = i - l * 3072;
    float v = (r < 1024) ? bq[l * 1024 + r]
            : (r < 2048) ? bk[l * 1024 + r - 1024]
                         : bv[l * 1024 + r - 2048];
    dst[i] = v;
}

// ---------------- mma.sync bf16 GEMM: C[2048,N] = A'[2048,K3] @ Bt'[N,K3]^T + bias ----------------
// 128x128 tile, BK=32, 3-stage cp.async pipeline, 8 warps (4 M x 2 N), warp tile 32x64.
__global__ void __launch_bounds__(256, 2)
mm_kernel(const __nv_bfloat16* __restrict__ A, const __nv_bfloat16* __restrict__ Bt,
          const float* __restrict__ bias, float* __restrict__ C,
          int N, int K3, int relu)
{
    __shared__ __align__(1024) char sm[3 * 16384];   // per stage: A 8KB | B 8KB

    const int tid = threadIdx.x;
    const int wid = tid >> 5, lane = tid & 31;
    const int wm = wid & 3, wn = wid >> 2;
    const int bx = blockIdx.x, by = blockIdx.y;

    const __nv_bfloat16* Ab = A  + (size_t)(by * 128) * K3;
    const __nv_bfloat16* Bb = Bt + (size_t)(bx * 128) * K3;
    const int nch = K3 >> 5;

    // per-thread cp.async slots: u in {tid, tid+256}; r = u>>2 (row), kc = u&3 (16B chunk)
    const int r_ld0 = tid >> 2, kc_ld = tid & 3;

    auto load_stage = [&](int ci, int st) {
        char* as = sm + st * 16384;
        char* bs = as + 8192;
        const __nv_bfloat16* ag = Ab + ci * 32;
        const __nv_bfloat16* bg = Bb + ci * 32;
#pragma unroll
        for (int i = 0; i < 2; i++) {
            int r = r_ld0 + i * 64;
            int so = swz(r, kc_ld);
            cp16(smem_u32(as + so), ag + (size_t)r * K3 + kc_ld * 8);
            cp16(smem_u32(bs + so), bg + (size_t)r * K3 + kc_ld * 8);
        }
        CP_COMMIT();
    };

    float acc[2][8][4];
#pragma unroll
    for (int m = 0; m < 2; m++)
#pragma unroll
        for (int n = 0; n < 8; n++)
#pragma unroll
            for (int j = 0; j < 4; j++) acc[m][n][j] = 0.0f;

    load_stage(0, 0);
    load_stage(1, 1);

    for (int ci = 0; ci < nch; ci++) {
        if (ci + 2 < nch) {
            load_stage(ci + 2, (ci + 2) % 3);
            asm volatile("cp.async.wait_group 2;" ::: "memory");
        } else if (ci + 1 < nch) {
            asm volatile("cp.async.wait_group 1;" ::: "memory");
        } else {
            asm volatile("cp.async.wait_group 0;" ::: "memory");
        }
        __syncthreads();

        char* as = sm + (ci % 3) * 16384;
        char* bs = as + 8192;
#pragma unroll
        for (int kh = 0; kh < 2; kh++) {
            const int kc0 = kh * 2;   // k16 half -> 16B chunk base
            uint32_t af[2][4], bf[4][4];
#pragma unroll
            for (int mt = 0; mt < 2; mt++) {
                int r = wm * 32 + mt * 16 + (lane & 15);
                int kc = kc0 + (lane >> 4);
                ldm_x4(af[mt][0], af[mt][1], af[mt][2], af[mt][3], smem_u32(as + swz(r, kc)));
            }
#pragma unroll
            for (int nt2 = 0; nt2 < 4; nt2++) {
                int g = lane >> 3;
                int r = wn * 64 + nt2 * 16 + ((g >> 1) << 3) + (lane & 7);
                int kc = kc0 + (g & 1);
                ldm_x4(bf[nt2][0], bf[nt2][1], bf[nt2][2], bf[nt2][3], smem_u32(bs + swz(r, kc)));
            }
#pragma unroll
            for (int mt = 0; mt < 2; mt++)
#pragma unroll
                for (int nt = 0; nt < 8; nt++)
                    mma16816(acc[mt][nt], af[mt], bf[nt >> 1][(nt & 1) * 2], bf[nt >> 1][(nt & 1) * 2 + 1]);
        }
        __syncthreads();
    }

    // epilogue
    const int row0 = by * 128 + wm * 32;
    const int col0 = bx * 128 + wn * 64;
#pragma unroll
    for (int mt = 0; mt < 2; mt++) {
#pragma unroll
        for (int nt = 0; nt < 8; nt++) {
            int c = col0 + nt * 8 + 2 * (lane & 3);
            float2 bv = *(const float2*)(bias + c);
            int r = row0 + mt * 16 + (lane >> 2);
            float v0 = acc[mt][nt][0] + bv.x;
            float v1 = acc[mt][nt][1] + bv.y;
            float v2 = acc[mt][nt][2] + bv.x;
            float v3 = acc[mt][nt][3] + bv.y;
            if (relu) {
                v0 = fmaxf(v0, 0.f); v1 = fmaxf(v1, 0.f);
                v2 = fmaxf(v2, 0.f); v3 = fmaxf(v3, 0.f);
            }
            float2 o0 = {v0, v1}, o1 = {v2, v3};
            *(float2*)(C + (size_t)r * N + c)       = o0;
            *(float2*)(C + (size_t)(r + 8) * N + c) = o1;
        }
    }
}

// ---------------- fused causal attention (flash-style), QKV strided (ld=3072) ----------------
__global__ void attn_kernel(const float* __restrict__ QKV, float* __restrict__ Og)
{
    extern __shared__ float smf[];
    float* qs = smf;
    float* kp = smf + 64 * 68;
    float* vs = smf + 2 * 64 * 68;

    const int qt = blockIdx.x, bh = blockIdx.y;
    const int b = bh >> 4, h = bh & 15;
    const int tid = threadIdx.x;
    const int r = tid >> 2, sub = tid & 3;
    const int LDQ = 3 * D_;
    const size_t qbase = ((size_t)b * S_) * LDQ + (size_t)h * 64;

    const float* qb = QKV + qbase + (size_t)(qt * 64) * LDQ;
    for (int idx = tid; idx < 1024; idx += 256) {
        int rr = idx >> 4, c = (idx & 15) << 2;
        float4 v = *(const float4*)(qb + (size_t)rr * LDQ + c);
        float4 vv = {v.x * 0.125f, v.y * 0.125f, v.z * 0.125f, v.w * 0.125f};
        *(float4*)&qs[rr * 68 + c] = vv;
    }

    float acc[16];
#pragma unroll
    for (int i = 0; i < 16; i++) acc[i] = 0.0f;
    float l = 0.0f, m = -1e30f;
    const int qglob = qt * 64 + r;

    for (int kt = 0; kt <= qt; kt++) {
        __syncthreads();
        const float* kb = QKV + qbase + 1024 + (size_t)(kt * 64) * LDQ;
        const float* vb = QKV + qbase + 2048 + (size_t)(kt * 64) * LDQ;
        for (int idx = tid; idx < 1024; idx += 256) {
            int rr = idx >> 4, c = (idx & 15) << 2;
            *(float4*)&kp[rr * 68 + c] = *(const float4*)(kb + (size_t)rr * LDQ + c);
            *(float4*)&vs[rr * 68 + c] = *(const float4*)(vb + (size_t)rr * LDQ + c);
        }
        __syncthreads();

        float s[16];
#pragma unroll
        for (int jj = 0; jj < 16; jj++) s[jj] = 0.0f;
#pragma unroll 4
        for (int d = 0; d < 64; d++) {
            float qd = qs[r * 68 + d];
#pragma unroll
            for (int jj = 0; jj < 16; jj++)
                s[jj] += qd * kp[(sub + (jj << 2)) * 68 + d];
        }
#pragma unroll
        for (int jj = 0; jj < 16; jj++) {
            int kg = kt * 64 + sub + (jj << 2);
            if (kg > qglob) s[jj] = -1e30f;
        }
        float mt = s[0];
#pragma unroll
        for (int jj = 1; jj < 16; jj++) mt = fmaxf(mt, s[jj]);
        mt = fmaxf(mt, __shfl_xor_sync(0xffffffffu, mt, 1));
        mt = fmaxf(mt, __shfl_xor_sync(0xffffffffu, mt, 2));
        float mnew = fmaxf(m, mt);
        float corr = __expf(m - mnew);
        float p[16];
        float ls = 0.0f;
#pragma unroll
        for (int jj = 0; jj < 16; jj++) { p[jj] = __expf(s[jj] - mnew); ls += p[jj]; }
        ls += __shfl_xor_sync(0xffffffffu, ls, 1);
        ls += __shfl_xor_sync(0xffffffffu, ls, 2);
        l = l * corr + ls;
        m = mnew;
#pragma unroll
        for (int i = 0; i < 16; i++) acc[i] *= corr;

        __syncthreads();
#pragma unroll
        for (int jj = 0; jj < 16; jj++) kp[r * 68 + sub + (jj << 2)] = p[jj];
        __syncwarp();
#pragma unroll 2
        for (int j = 0; j < 64; j++) {
            float pj = kp[r * 68 + j];
            float4 v0 = *(const float4*)&vs[j * 68 + sub * 16];
            float4 v1 = *(const float4*)&vs[j * 68 + sub * 16 + 4];
            float4 v2 = *(const float4*)&vs[j * 68 + sub * 16 + 8];
            float4 v3 = *(const float4*)&vs[j * 68 + sub * 16 + 12];
            acc[0]  += pj * v0.x; acc[1]  += pj * v0.y; acc[2]  += pj * v0.z; acc[3]  += pj * v0.w;
            acc[4]  += pj * v1.x; acc[5]  += pj * v1.y; acc[6]  += pj * v1.z; acc[7]  += pj * v1.w;
            acc[8]  += pj * v2.x; acc[9]  += pj * v2.y; acc[10] += pj * v2.z; acc[11] += pj * v2.w;
            acc[12] += pj * v3.x; acc[13] += pj * v3.y; acc[14] += pj * v3.z; acc[15] += pj * v3.w;
        }
    }

    float inv = 1.0f / (l + 1e-9f);
    float* ob = Og + ((size_t)b * S_ + qglob) * D_ + (size_t)h * 64 + sub * 16;
    float4 o0 = {acc[0] * inv,  acc[1] * inv,  acc[2] * inv,  acc[3] * inv};
    float4 o1 = {acc[4] * inv,  acc[5] * inv,  acc[6] * inv,  acc[7] * inv};
    float4 o2 = {acc[8] * inv,  acc[9] * inv,  acc[10] * inv, acc[11] * inv};
    float4 o3 = {acc[12] * inv, acc[13] * inv, acc[14] * inv, acc[15] * inv};
    *(float4*)(ob)      = o0;
    *(float4*)(ob + 4)  = o1;
    *(float4*)(ob + 8)  = o2;
    *(float4*)(ob + 12) = o3;
}

// ---------------- t = x + delta; out = LN(t)*g + b + delta ----------------
__global__ void add_ln_kernel(const float* __restrict__ x, const float* __restrict__ dl,
                              const float* __restrict__ g, const float* __restrict__ bb,
                              float* __restrict__ out)
{
    const int row = blockIdx.x, tid = threadIdx.x;
    const float4* xr = (const float4*)(x  + (size_t)row * D_);
    const float4* dr = (const float4*)(dl + (size_t)row * D_);
    float4 xv = xr[tid], dv = dr[tid];
    float4 t = {xv.x + dv.x, xv.y + dv.y, xv.z + dv.z, xv.w + dv.w};

    __shared__ float red[8];
    float s = t.x + t.y + t.z + t.w;
#pragma unroll
    for (int off = 16; off; off >>= 1) s += __shfl_xor_sync(0xffffffffu, s, off);
    if ((tid & 31) == 0) red[tid >> 5] = s;
    __syncthreads();
    float mu = (red[0] + red[1] + red[2] + red[3] + red[4] + red[5] + red[6] + red[7]) * (1.0f / D_);
    __syncthreads();

    float d0 = t.x - mu, d1 = t.y - mu, d2 = t.z - mu, d3 = t.w - mu;
    float sq = d0 * d0 + d1 * d1 + d2 * d2 + d3 * d3;
#pragma unroll
    for (int off = 16; off; off >>= 1) sq += __shfl_xor_sync(0xffffffffu, sq, off);
    if ((tid & 31) == 0) red[tid >> 5] = sq;
    __syncthreads();
    float var = (red[0] + red[1] + red[2] + red[3] + red[4] + red[5] + red[6] + red[7]) * (1.0f / D_);
    float rinv = rsqrtf(var + 1e-5f);

    float4 gv = ((const float4*)g)[tid];
    float4 bv = ((const float4*)bb)[tid];
    float4 o;
    o.x = d0 * rinv * gv.x + bv.x + dv.x;
    o.y = d1 * rinv * gv.y + bv.y + dv.y;
    o.z = d2 * rinv * gv.z + bv.z + dv.z;
    o.w = d3 * rinv * gv.w + bv.w + dv.w;
    ((float4*)(out + (size_t)row * D_))[tid] = o;
}

// ---------------- head reduce: out[bs,o] = hid[bs, o*1024 + :] . hw2[o] + hb2[o] ----------------
__global__ void head_reduce_kernel(const float* __restrict__ hid, const float* __restrict__ w2,
                                   const float* __restrict__ b2, float* __restrict__ out)
{
    const int bs = blockIdx.x, o = blockIdx.y;
    const float4* hr = (const float4*)(hid + (size_t)bs * (3 * D_) + (size_t)o * D_);
    const float4* wr = (const float4*)(w2 + (size_t)o * D_);
    const int tid = threadIdx.x;
    float4 hv = hr[tid], wv = wr[tid];
    float s = hv.x * wv.x + hv.y * wv.y + hv.z * wv.z + hv.w * wv.w;
#pragma unroll
    for (int off = 16; off; off >>= 1) s += __shfl_xor_sync(0xffffffffu, s, off);
    __shared__ float red[8];
    if ((tid & 31) == 0) red[tid >> 5] = s;
    __syncthreads();
    if (tid == 0) {
        float t = red[0] + red[1] + red[2] + red[3] + red[4] + red[5] + red[6] + red[7];
        out[bs * 3 + o] = t + b2[o];
    }
}

// ---------------- launch ----------------
extern "C" void kernel_launch(void* const* d_in, const int* in_sizes, int n_in,
                              void* d_out, int out_size)
{
    const float* src   = (const float*)d_in[0];
    const float* emb_w = (const float*)d_in[1];
    const float* emb_b = (const float*)d_in[2];
    const float* pe    = (const float*)d_in[3];
    const float* Wq    = (const float*)d_in[4];
    const float* bq    = (const float*)d_in[5];
    const float* Wk    = (const float*)d_in[6];
    const float* bk    = (const float*)d_in[7];
    const float* Wv    = (const float*)d_in[8];
    const float* bv    = (const float*)d_in[9];
    const float* Wo    = (const float*)d_in[10];
    const float* bo    = (const float*)d_in[11];
    const float* fc1_w = (const float*)d_in[12];
    const float* fc1_b = (const float*)d_in[13];
    const float* fc2_w = (const float*)d_in[14];
    const float* fc2_b = (const float*)d_in[15];
    const float* ln1_g = (const float*)d_in[16];
    const float* ln1_b = (const float*)d_in[17];
    const float* ln2_g = (const float*)d_in[18];
    const float* ln2_b = (const float*)d_in[19];
    const float* hw1   = (const float*)d_in[20];
    const float* hb1   = (const float*)d_in[21];
    const float* hw2   = (const float*)d_in[22];
    const float* hb2   = (const float*)d_in[23];

    float *x, *qkv, *attn, *obuf, *ff1, *hid, *bqkv;
    __nv_bfloat16 *aext, *wqkv, *wo, *wf1, *wf2, *wh;
    cudaGetSymbolAddress((void**)&x,    g_x);
    cudaGetSymbolAddress((void**)&qkv,  g_qkv);
    cudaGetSymbolAddress((void**)&attn, g_attn);
    cudaGetSymbolAddress((void**)&obuf, g_obuf);
    cudaGetSymbolAddress((void**)&ff1,  g_ff1);
    cudaGetSymbolAddress((void**)&hid,  g_hid);
    cudaGetSymbolAddress((void**)&bqkv, g_bqkv);
    cudaGetSymbolAddress((void**)&aext, g_aext);
    cudaGetSymbolAddress((void**)&wqkv, g_wqkv);
    cudaGetSymbolAddress((void**)&wo,   g_wo);
    cudaGetSymbolAddress((void**)&wf1,  g_wf1);
    cudaGetSymbolAddress((void**)&wf2,  g_wf2);
    cudaGetSymbolAddress((void**)&wh,   g_wh);

    const int ATTN_SMEM = 3 * 64 * 68 * 4;
    cudaFuncSetAttribute(attn_kernel, cudaFuncAttributeMaxDynamicSharedMemorySize, ATTN_SMEM);

    const size_t DD  = (size_t)D_ * D_;
    const size_t K3D = 3 * (size_t)D_;       // 3072
    const size_t K3F = 3 * (size_t)DFF_;     // 12288

    // --- weight + bias conversions ---
    dim3 cwtB(32, 8);
    for (int l = 0; l < L_; l++) {
        __nv_bfloat16* wq_dst = wqkv + (size_t)l * K3D * K3D;     // [3072, 3072]
        conv_wt<<<dim3(32, 32), cwtB>>>(Wq + l * DD, wq_dst,                    D_, D_);
        conv_wt<<<dim3(32, 32), cwtB>>>(Wk + l * DD, wq_dst + 1024 * K3D,       D_, D_);
        conv_wt<<<dim3(32, 32), cwtB>>>(Wv + l * DD, wq_dst + 2048 * K3D,       D_, D_);
        conv_wt<<<dim3(32, 32), cwtB>>>(Wo + l * DD, wo + (size_t)l * D_ * K3D, D_, D_);
        conv_wt<<<dim3(128, 32), cwtB>>>(fc1_w + (size_t)l * D_ * DFF_,
                                         wf1 + (size_t)l * DFF_ * K3D, D_, DFF_);
        conv_wt<<<dim3(32, 128), cwtB>>>(fc2_w + (size_t)l * DFF_ * D_,
                                         wf2 + (size_t)l * D_ * K3F, DFF_, D_);
    }
    for (int o = 0; o < 3; o++)
        conv_wt<<<dim3(32, 32), cwtB>>>(hw1 + (size_t)o * DD, wh + (size_t)o * D_ * K3D, D_, D_);
    pack_bias<<<L_ * 3 * D_ / 256, 256>>>(bq, bk, bv, bqkv);

    // --- forward ---
    embed_kernel<<<ROWS_ * D_ / 4 / 256, 256>>>(src, emb_w, emb_b, pe);

    for (int l = 0; l < L_; l++) {
        size_t bof = (size_t)l * D_;
        // QKV fused: [2048,3072] = x' @ wqkv^T
        conv_act<<<ROWS_ * D_ / 4 / 256, 256>>>(x, aext, D_);
        mm_kernel<<<dim3(24, 16), 256>>>(aext, wqkv + (size_t)l * K3D * K3D,
                                         bqkv + (size_t)l * K3D, qkv, 3 * D_, (int)K3D, 0);
        attn_kernel<<<dim3(S_ / 64, B_ * H_), 256, ATTN_SMEM>>>(qkv, attn);
        conv_act<<<ROWS_ * D_ / 4 / 256, 256>>>(attn, aext, D_);
        mm_kernel<<<dim3(8, 16), 256>>>(aext, wo + (size_t)l * D_ * K3D,
                                        bo + bof, obuf, D_, (int)K3D, 0);
        add_ln_kernel<<<ROWS_, 256>>>(x, obuf, ln1_g + bof, ln1_b + bof, x);
        conv_act<<<ROWS_ * D_ / 4 / 256, 256>>>(x, aext, D_);
        mm_kernel<<<dim3(32, 16), 256>>>(aext, wf1 + (size_t)l * DFF_ * K3D,
                                         fc1_b + (size_t)l * DFF_, ff1, DFF_, (int)K3D, 1);
        conv_act<<<ROWS_ * DFF_ / 4 / 256, 256>>>(ff1, aext, DFF_);
        mm_kernel<<<dim3(8, 16), 256>>>(aext, wf2 + (size_t)l * D_ * K3F,
                                        fc2_b + bof, obuf, D_, (int)K3F, 1);
        add_ln_kernel<<<ROWS_, 256>>>(x, obuf, ln2_g + bof, ln2_b + bof, x);
    }

    // heads: [2048, 3072] = x' @ wh^T, relu, then per-head dot
    conv_act<<<ROWS_ * D_ / 4 / 256, 256>>>(x, aext, D_);
    mm_kernel<<<dim3(24, 16), 256>>>(aext, wh, hb1, hid, 3 * D_, (int)K3D, 1);
    head_reduce_kernel<<<dim3(ROWS_, 3), 256>>>(hid, hw2, hb2, (float*)d_out);
}